// round 16
// baseline (speedup 1.0000x reference)
#include <cuda_runtime.h>
#include <cstdint>

// CTC forward — one warp/batch, scaled-linear forward, BLOCKED layout:
// lane j holds alpha[4j..4j+3] (+ s=128 in lane 31). One shfl per step.
// Renorm every 8 steps; DEFERRED SCAN: the runmax scan reference is computed
// from the step-6 snapshot so the 5-hop shfl chain + log overlap steps 7-8
// (values grow <= x3/step -> R(6) bounds L(8)-2.2 nats; same safety envelope).
// Cheap two-stage rescale a*(s2)*(s2), s2 = exp((c-nc)/2): exact, no clamp.

#define CTC_B   256
#define CTC_T   512
#define CTC_C   128
#define CTC_L   64
#define BLANK   (CTC_C - 1)
#define WPC     2
#define MACRO   8
#define NMACRO  (CTC_T / MACRO)   // 64
#define EPS_F   1e-7f
#define FM      0xffffffffu
#define BIAS    40.0f
#define MFLOOR  1e-37f

__device__ __forceinline__ void cp_async16(void* smem_dst, const void* gmem_src) {
    unsigned saddr = (unsigned)__cvta_generic_to_shared(smem_dst);
    asm volatile("cp.async.cg.shared.global [%0], [%1], 16;\n"
                 :: "r"(saddr), "l"(gmem_src) : "memory");
}
#define CP_COMMIT() asm volatile("cp.async.commit_group;\n" ::: "memory")
#define CP_WAIT(n)  asm volatile("cp.async.wait_group %0;\n" :: "n"(n) : "memory")

__global__ __launch_bounds__(WPC * 32, 1)
void ctc_loss_kernel(const float* __restrict__ y_pred,
                     const int*   __restrict__ labels,
                     const int*   __restrict__ input_length,
                     const int*   __restrict__ label_length,
                     float*       __restrict__ out)
{
    __shared__ float rings[WPC][3][MACRO][CTC_C];   // 24 KB
    const int wid  = threadIdx.x >> 5;
    const int lane = threadIdx.x & 31;
    const int b = blockIdx.x * WPC + wid;
    const float* __restrict__ yb = y_pred + (size_t)b * CTC_T * CTC_C;
    float (*ring)[MACRO][CTC_C] = rings[wid];

    const int l     = label_length[b];
    const int t_idx = input_length[b] - 1;

    // labels: lane j covers odd states 4j+1 (label 2j) and 4j+3 (label 2j+1)
    const int labA = labels[b * CTC_L + 2 * lane];
    const int labB = labels[b * CTC_L + 2 * lane + 1];
    const int labBm = __shfl_up_sync(FM, labB, 1);          // lab[2j-1]
    const float sk1 = ((lane > 0) && (labA != labBm)) ? 1.0f : 0.0f;  // s=4j+1
    const float sk3 = (labB != labA) ? 1.0f : 0.0f;                   // s=4j+3
    const float e64m = (lane == 31) ? 1.0f : 0.0f;

    // prologue: macros 0,1 in flight
    #pragma unroll
    for (int mb = 0; mb < 2; ++mb) {
        #pragma unroll
        for (int r = 0; r < MACRO; ++r)
            cp_async16(&ring[mb][r][lane * 4],
                       yb + (size_t)(mb * MACRO + r) * CTC_C + lane * 4);
        CP_COMMIT();
    }
    CP_WAIT(1);
    __syncwarp();

    // state (values in lane scale c), cross-lane factor f
    float a0 = (lane == 0) ? 1.0f : 0.0f;   // seed: generic step at t=0 gives alpha0
    float a1 = 0.f, a2 = 0.f, a3 = 0.f, e64 = 0.f;
    float c = 0.f;
    float f  = (lane == 0) ? 0.f : 1.f;
    float fs1 = sk1 * f;

    // snapshot at t_idx
    float cv0 = 0.f, cv1 = 0.f, cv2 = 0.f, cv3 = 0.f, cve = 0.f, cvc = 0.f;

    const int mcap = t_idx >> 3;    // warp-uniform
    const int rcap = t_idx & 7;

    float Pb[MACRO], P0[MACRO], P1[MACRO];
    {
        const float (*rows)[CTC_C] = ring[0];
        #pragma unroll
        for (int r = 0; r < MACRO; ++r) {
            Pb[r] = rows[r][BLANK] + EPS_F;
            P0[r] = rows[r][labA] + EPS_F;
            P1[r] = rows[r][labB] + EPS_F;
        }
    }

    float Mdef = 0.0f;     // deferred scan reference (set at r==5 each macro)

    #define CTC_STEP(r)                                                   \
    {                                                                     \
        float x = __shfl_up_sync(FM, a3, 1);   /* alpha[4j-1]; lane0 f=0 */\
        float ne = (e64 + a3) * Pb[r];         /* s=128 (lane31 only) */  \
        float s23 = a3 + a2;                                              \
        float na3 = fmaf(sk3, a1, s23) * P1[r];                           \
        float na2 = (a2 + a1) * Pb[r];                                    \
        float s01 = a1 + a0;                                              \
        float na1 = fmaf(fs1, x, s01) * P0[r];                            \
        float na0 = fmaf(f, x, a0) * Pb[r];                               \
        a0 = na0; a1 = na1; a2 = na2; a3 = na3; e64 = ne;                 \
    }

    // deferred snapshot of the lane max at step 6 (r == 5)
    #define CTC_SNAP6(r)                                                  \
    if (r == 5) {                                                         \
        float smax = fmaxf(fmaxf(a0, a1), fmaxf(a2, a3));                 \
        smax = fmaxf(smax, e64 * e64m);                                   \
        Mdef = c + __logf(fmaxf(smax, MFLOOR));                           \
    }

    for (int m = 0; m < NMACRO; ++m) {
        // issue macro m+2
        if (m + 2 < NMACRO) {
            float* dst = &ring[(m + 2) % 3][0][0];
            const float* src = yb + (size_t)(m + 2) * MACRO * CTC_C;
            #pragma unroll
            for (int r = 0; r < MACRO; ++r)
                cp_async16(dst + r * CTC_C + lane * 4, src + r * CTC_C + lane * 4);
        }
        CP_COMMIT();

        if (m == mcap) {
            #pragma unroll
            for (int r = 0; r < MACRO; ++r) {
                CTC_STEP(r);
                CTC_SNAP6(r);
                if (r == rcap) {
                    cv0 = a0; cv1 = a1; cv2 = a2; cv3 = a3; cve = e64; cvc = c;
                }
            }
        } else {
            #pragma unroll
            for (int r = 0; r < MACRO; ++r) {
                CTC_STEP(r);
                CTC_SNAP6(r);
            }
        }

        // runmax scan on the DEFERRED reference (overlaps steps 7-8 via ILP;
        // written here so ptxas can hoist the independent hops upward)
        float R = Mdef;
        #pragma unroll
        for (int d = 1; d < 32; d <<= 1)
            R = fmaxf(R, __shfl_up_sync(FM, R, d));      // monotone in lane

        // next macro resident; prefetch its p's (hides under renorm tail)
        CP_WAIT(1);
        __syncwarp();
        if (m + 1 < NMACRO) {
            const float (*rows)[CTC_C] = ring[(m + 1) % 3];
            #pragma unroll
            for (int r = 0; r < MACRO; ++r) {
                Pb[r] = rows[r][BLANK] + EPS_F;
                P0[r] = rows[r][labA] + EPS_F;
                P1[r] = rows[r][labB] + EPS_F;
            }
        }

        // ---- renorm tail: nc -> f, s2 -> rescale ----
        {
            float nc = R - BIAS;
            float ncm = __shfl_up_sync(FM, nc, 1);
            f = (lane == 0) ? 0.f : __expf(fminf(ncm - nc, 0.0f));  // <= 1
            fs1 = sk1 * f;
            float s2 = __expf(0.5f * (c - nc));          // two-stage: exact, no clamp
            a0 = (a0 * s2) * s2;
            a1 = (a1 * s2) * s2;
            a2 = (a2 * s2) * s2;
            a3 = (a3 * s2) * s2;
            e64 = (e64 * s2) * s2;
            c = nc;
        }
    }
    #undef CTC_STEP
    #undef CTC_SNAP6

    // ---- extract loss = -logaddexp(L[2l], L[2l-1]) at t_idx ----
    float a_last;
    if (l == 64) {                                       // warp-uniform
        float v  = __shfl_sync(FM, cve, 31);
        float cc = __shfl_sync(FM, cvc, 31);
        a_last = cc + __logf(fmaxf(v, MFLOOR));
    } else {
        const int sE = 2 * l, ln = sE >> 2, ix = sE & 3; // ix in {0,2}
        float g0 = __shfl_sync(FM, cv0, ln);
        float g2 = __shfl_sync(FM, cv2, ln);
        float cc = __shfl_sync(FM, cvc, ln);
        a_last = cc + __logf(fmaxf(ix ? g2 : g0, MFLOOR));
    }
    {
        const int sP = 2 * l - 1, ln = sP >> 2, ix = sP & 3;  // ix in {1,3}
        float g1 = __shfl_sync(FM, cv1, ln);
        float g3 = __shfl_sync(FM, cv3, ln);
        float cc = __shfl_sync(FM, cvc, ln);
        float a_prev = cc + __logf(fmaxf((ix == 3) ? g3 : g1, MFLOOR));
        if (lane == 0) {
            float mx = fmaxf(a_last, a_prev);
            out[b] = -(mx + __logf(__expf(a_last - mx) + __expf(a_prev - mx)));
        }
    }
}

extern "C" void kernel_launch(void* const* d_in, const int* in_sizes, int n_in,
                              void* d_out, int out_size) {
    const float* y_pred       = (const float*)d_in[0];
    const int*   labels       = (const int*)  d_in[1];
    const int*   input_length = (const int*)  d_in[2];
    const int*   label_length = (const int*)  d_in[3];
    float*       out          = (float*)d_out;

    ctc_loss_kernel<<<CTC_B / WPC, WPC * 32>>>(y_pred, labels, input_length, label_length, out);
}

// round 17
// speedup vs baseline: 1.4012x; 1.4012x over previous
#include <cuda_runtime.h>
#include <cstdint>

// CTC forward — one warp/batch, scaled-linear forward, BLOCKED layout:
// lane j holds alpha[8..] wait: alpha[4j..4j+3] (+ s=128 in lane 31). One shfl/step.
// Renorm every 8 steps with:
//   (1) DEFERRED runmax scan (reference snapped at step 6, scan overlaps steps 7-8)
//   (2) FOLDED rescale: s^2 is multiplied into the NEXT macro's first-step P
//       (off the alpha chain); step 0 of each macro uses the OLD cross-lane f
//       (exp(c_old_m - c_old)), steps 1-7 the new f. Alpha chain never stalls
//       for renorm. gap clamped at 80, two-stage fold (no overflow; flushes
//       only lanes >= ~85 nats below the running max — refilled by inflow).

#define CTC_B   256
#define CTC_T   512
#define CTC_C   128
#define CTC_L   64
#define BLANK   (CTC_C - 1)
#define WPC     2
#define MACRO   8
#define NMACRO  (CTC_T / MACRO)   // 64
#define EPS_F   1e-7f
#define FM      0xffffffffu
#define BIAS    40.0f
#define MFLOOR  1e-37f

__device__ __forceinline__ void cp_async16(void* smem_dst, const void* gmem_src) {
    unsigned saddr = (unsigned)__cvta_generic_to_shared(smem_dst);
    asm volatile("cp.async.cg.shared.global [%0], [%1], 16;\n"
                 :: "r"(saddr), "l"(gmem_src) : "memory");
}
#define CP_COMMIT() asm volatile("cp.async.commit_group;\n" ::: "memory")
#define CP_WAIT(n)  asm volatile("cp.async.wait_group %0;\n" :: "n"(n) : "memory")

__global__ __launch_bounds__(WPC * 32, 1)
void ctc_loss_kernel(const float* __restrict__ y_pred,
                     const int*   __restrict__ labels,
                     const int*   __restrict__ input_length,
                     const int*   __restrict__ label_length,
                     float*       __restrict__ out)
{
    __shared__ float rings[WPC][3][MACRO][CTC_C];   // 24 KB
    const int wid  = threadIdx.x >> 5;
    const int lane = threadIdx.x & 31;
    const int b = blockIdx.x * WPC + wid;
    const float* __restrict__ yb = y_pred + (size_t)b * CTC_T * CTC_C;
    float (*ring)[MACRO][CTC_C] = rings[wid];

    const int l     = label_length[b];
    const int t_idx = input_length[b] - 1;

    // labels: lane j covers odd states 4j+1 (label 2j) and 4j+3 (label 2j+1)
    const int labA = labels[b * CTC_L + 2 * lane];
    const int labB = labels[b * CTC_L + 2 * lane + 1];
    const int labBm = __shfl_up_sync(FM, labB, 1);          // lab[2j-1]
    const float sk1 = ((lane > 0) && (labA != labBm)) ? 1.0f : 0.0f;  // s=4j+1
    const float sk3 = (labB != labA) ? 1.0f : 0.0f;                   // s=4j+3
    const float e64m = (lane == 31) ? 1.0f : 0.0f;

    // prologue: macros 0,1 in flight
    #pragma unroll
    for (int mb = 0; mb < 2; ++mb) {
        #pragma unroll
        for (int r = 0; r < MACRO; ++r)
            cp_async16(&ring[mb][r][lane * 4],
                       yb + (size_t)(mb * MACRO + r) * CTC_C + lane * 4);
        CP_COMMIT();
    }
    CP_WAIT(1);
    __syncwarp();

    // state (values in lane scale c), cross-lane factor f
    float a0 = (lane == 0) ? 1.0f : 0.0f;   // seed: generic step at t=0 gives alpha0
    float a1 = 0.f, a2 = 0.f, a3 = 0.f, e64 = 0.f;
    float c = 0.f;
    float f      = (lane == 0) ? 0.f : 1.f;
    float f_pend = f;                        // becomes active after step 0 of each macro
    float fs1 = sk1 * f;

    // snapshot at t_idx
    float cv0 = 0.f, cv1 = 0.f, cv2 = 0.f, cv3 = 0.f, cve = 0.f, cvc = 0.f;

    const int mcap = t_idx >> 3;    // warp-uniform
    const int rcap = t_idx & 7;

    float Pb[MACRO], P0[MACRO], P1[MACRO];
    {
        const float (*rows)[CTC_C] = ring[0];
        #pragma unroll
        for (int r = 0; r < MACRO; ++r) {
            Pb[r] = rows[r][BLANK] + EPS_F;
            P0[r] = rows[r][labA] + EPS_F;
            P1[r] = rows[r][labB] + EPS_F;
        }
    }

    float Mdef = 0.0f;     // deferred scan reference (set at r==5 each macro)

    #define CTC_STEP(r)                                                   \
    {                                                                     \
        float x = __shfl_up_sync(FM, a3, 1);   /* alpha[4j-1]; lane0 f=0 */\
        float ne = (e64 + a3) * Pb[r];         /* s=128 (lane31 only) */  \
        float s23 = a3 + a2;                                              \
        float na3 = fmaf(sk3, a1, s23) * P1[r];                           \
        float na2 = (a2 + a1) * Pb[r];                                    \
        float s01 = a1 + a0;                                              \
        float na1 = fmaf(fs1, x, s01) * P0[r];                            \
        float na0 = fmaf(f, x, a0) * Pb[r];                               \
        a0 = na0; a1 = na1; a2 = na2; a3 = na3; e64 = ne;                 \
    }

    #define CTC_CAP(r)                                                    \
    if (r == rcap) { cv0 = a0; cv1 = a1; cv2 = a2; cv3 = a3;              \
                     cve = e64; cvc = c; }

    // deferred snapshot of the lane max at step 6 (r == 5)
    #define CTC_SNAP6()                                                   \
    {                                                                     \
        float smax = fmaxf(fmaxf(a0, a1), fmaxf(a2, a3));                 \
        smax = fmaxf(smax, e64 * e64m);                                   \
        Mdef = c + __logf(fmaxf(smax, MFLOOR));                           \
    }

    for (int m = 0; m < NMACRO; ++m) {
        // issue macro m+2
        if (m + 2 < NMACRO) {
            float* dst = &ring[(m + 2) % 3][0][0];
            const float* src = yb + (size_t)(m + 2) * MACRO * CTC_C;
            #pragma unroll
            for (int r = 0; r < MACRO; ++r)
                cp_async16(dst + r * CTC_C + lane * 4, src + r * CTC_C + lane * 4);
        }
        CP_COMMIT();

        const bool capm = (m == mcap);        // warp-uniform

        // step 0 runs with OLD f (its P carries the folded rescale);
        // then switch to the pending (post-renorm) f for steps 1-7.
        CTC_STEP(0);
        if (capm) { CTC_CAP(0); }
        f = f_pend; fs1 = sk1 * f;

        if (capm) {
            #pragma unroll
            for (int r = 1; r < MACRO; ++r) {
                CTC_STEP(r);
                if (r == 5) CTC_SNAP6();
                CTC_CAP(r);
            }
        } else {
            #pragma unroll
            for (int r = 1; r < MACRO; ++r) {
                CTC_STEP(r);
                if (r == 5) CTC_SNAP6();
            }
        }

        if (m + 1 < NMACRO) {
            // runmax scan on the DEFERRED reference (overlaps steps 7-8 via ILP)
            float R = Mdef;
            #pragma unroll
            for (int d = 1; d < 32; d <<= 1)
                R = fmaxf(R, __shfl_up_sync(FM, R, d));      // monotone in lane

            // next macro resident; prefetch its p's
            CP_WAIT(1);
            __syncwarp();
            const float (*rows)[CTC_C] = ring[(m + 1) % 3];
            #pragma unroll
            for (int r = 0; r < MACRO; ++r) {
                Pb[r] = rows[r][BLANK] + EPS_F;
                P0[r] = rows[r][labA] + EPS_F;
                P1[r] = rows[r][labB] + EPS_F;
            }

            // renorm tail — entirely off the alpha chain:
            float nc  = R - BIAS;
            float ncm = __shfl_up_sync(FM, nc, 1);
            f_pend = (lane == 0) ? 0.f : __expf(fminf(ncm - nc, 0.0f));  // <= 1
            // fold rescale s^2 = e^{c-nc} into next macro's first-step P
            // (two-stage, gap clamped: sh <= e^40, P*sh*sh <= e^80 — no overflow)
            float sh = __expf(0.5f * fminf(c - nc, 80.0f));
            Pb[0] = (Pb[0] * sh) * sh;
            P0[0] = (P0[0] * sh) * sh;
            P1[0] = (P1[0] * sh) * sh;
            c = nc;
        }
    }
    #undef CTC_STEP
    #undef CTC_CAP
    #undef CTC_SNAP6

    // ---- extract loss = -logaddexp(L[2l], L[2l-1]) at t_idx ----
    float a_last;
    if (l == 64) {                                       // warp-uniform
        float v  = __shfl_sync(FM, cve, 31);
        float cc = __shfl_sync(FM, cvc, 31);
        a_last = cc + __logf(fmaxf(v, MFLOOR));
    } else {
        const int sE = 2 * l, ln = sE >> 2, ix = sE & 3; // ix in {0,2}
        float g0 = __shfl_sync(FM, cv0, ln);
        float g2 = __shfl_sync(FM, cv2, ln);
        float cc = __shfl_sync(FM, cvc, ln);
        a_last = cc + __logf(fmaxf(ix ? g2 : g0, MFLOOR));
    }
    {
        const int sP = 2 * l - 1, ln = sP >> 2, ix = sP & 3;  // ix in {1,3}
        float g1 = __shfl_sync(FM, cv1, ln);
        float g3 = __shfl_sync(FM, cv3, ln);
        float cc = __shfl_sync(FM, cvc, ln);
        float a_prev = cc + __logf(fmaxf((ix == 3) ? g3 : g1, MFLOOR));
        if (lane == 0) {
            float mx = fmaxf(a_last, a_prev);
            out[b] = -(mx + __logf(__expf(a_last - mx) + __expf(a_prev - mx)));
        }
    }
}

extern "C" void kernel_launch(void* const* d_in, const int* in_sizes, int n_in,
                              void* d_out, int out_size) {
    const float* y_pred       = (const float*)d_in[0];
    const int*   labels       = (const int*)  d_in[1];
    const int*   input_length = (const int*)  d_in[2];
    const int*   label_length = (const int*)  d_in[3];
    float*       out          = (float*)d_out;

    ctc_loss_kernel<<<CTC_B / WPC, WPC * 32>>>(y_pred, labels, input_length, label_length, out);
}